// round 13
// baseline (speedup 1.0000x reference)
#include <cuda_runtime.h>
#include <cuda_fp16.h>

// Inputs (metadata order):
//  0 embed  [N,64] f32          (N=1500)
//  1 edge_index [2,E]           (E=65536; int32 OR int64, per-warp sniffed)
//  2 noise  [N*N] f32
//  3 tmp    [1] f32
//  4 W1     [128,64] f32
//  5 b1     [64] f32
//  6 W2     [64,1] f32
//  7 b2     [1] f32
// Output: edge_mask [E] f32

#define MAXN 1500

// Per node n, row of 128 halfs: [0:64) = h1[n]+b1, [64:128) = h2[n]  (384 KB)
__device__ __align__(256) __half g_h16[MAXN * 128];

// ---------------------------------------------------------------------------
// Kernel 1: h table (fp16). 8 nodes per 256-thread block -> 188 blocks,
// ~1.27 blocks/SM (the 16-node version ran only 94 blocks = 1/3 chip idle).
// Thread t: node t>>5, half (t>>4)&1, k-quad (t&15)*4.
// ---------------------------------------------------------------------------
__global__ void __launch_bounds__(256) precompute_h(
    const float* __restrict__ embed,
    const float* __restrict__ W1,
    const float* __restrict__ b1,
    int N)
{
    __shared__ float se[8 * 64];
    int t  = threadIdx.x;
    int n0 = blockIdx.x * 8;

#pragma unroll
    for (int idx = t; idx < 512; idx += 256) {
        int nl = idx >> 6, f = idx & 63;
        se[idx] = (n0 + nl < N) ? embed[(n0 + nl) * 64 + f] : 0.0f;
    }
    __syncthreads();

    int nl   = t >> 5;            // node-local 0..7
    int half = (t >> 4) & 1;      // 0 -> h1, 1 -> h2
    int k0   = (t & 15) * 4;      // 4 adjacent k
    int node = n0 + nl;

    const float* es = se + nl * 64;
    float4 s = make_float4(0.f, 0.f, 0.f, 0.f);
#pragma unroll
    for (int f = 0; f < 64; f++) {
        float e = es[f];
        float4 w = *(const float4*)&W1[(half * 64 + f) * 64 + k0];
        s.x = fmaf(e, w.x, s.x);
        s.y = fmaf(e, w.y, s.y);
        s.z = fmaf(e, w.z, s.z);
        s.w = fmaf(e, w.w, s.w);
    }
    if (half == 0) {
        float4 bb = *(const float4*)&b1[k0];
        s.x += bb.x; s.y += bb.y; s.z += bb.z; s.w += bb.w;
    }
    if (node < N) {
        __half2 lo = __floats2half2_rn(s.x, s.y);
        __half2 hi = __floats2half2_rn(s.z, s.w);
        uint2 p; p.x = *(unsigned*)&lo; p.y = *(unsigned*)&hi;
        *(uint2*)&g_h16[node * 128 + half * 64 + k0] = p;
    }
}

// 8 halfs (one uint4 of fp16 h) -> relu(a+c) dot W2[8]
__device__ __forceinline__ float dot8(uint4 a, uint4 c, float4 wa, float4 wb)
{
    const __half2* ah = (const __half2*)&a;
    const __half2* ch = (const __half2*)&c;
    const __half2  z  = __float2half2_rn(0.0f);
    float2 f0 = __half22float2(__hmax2(__hadd2(ah[0], ch[0]), z));
    float2 f1 = __half22float2(__hmax2(__hadd2(ah[1], ch[1]), z));
    float2 f2 = __half22float2(__hmax2(__hadd2(ah[2], ch[2]), z));
    float2 f3 = __half22float2(__hmax2(__hadd2(ah[3], ch[3]), z));
    float s = f0.x * wa.x;
    s = fmaf(f0.y, wa.y, s);
    s = fmaf(f1.x, wa.z, s);
    s = fmaf(f1.y, wa.w, s);
    s = fmaf(f2.x, wb.x, s);
    s = fmaf(f2.y, wb.y, s);
    s = fmaf(f3.x, wb.z, s);
    s = fmaf(f3.y, wb.w, s);
    return s;
}

// ---------------------------------------------------------------------------
// Kernel 2 (R11 best config): 4 edges per warp = 2 software-pipelined batches
// of the 8-lanes-per-row layout. All loads issue before any consumption.
//   grp = lane>>3 (direction 0..3 of a batch), m = lane&7 (8 k's),
//   el = grp>>1 (edge-in-batch), top = grp&1.
// ---------------------------------------------------------------------------
__global__ void __launch_bounds__(256) edge_gate(
    const void* __restrict__ ei_raw,
    const float* __restrict__ noise,
    const float* __restrict__ tmpp,
    const float* __restrict__ W2,
    const float* __restrict__ b2,
    float* __restrict__ out,
    int N, int E)
{
    int tid   = threadIdx.x;
    int lane  = tid & 31;
    int gwarp = (blockIdx.x * blockDim.x + tid) >> 5;
    int base  = gwarp * 4;            // 4 edges per warp

    int grp = lane >> 3;              // direction 0..3 (within a batch)
    int m   = lane & 7;               // eighth of the 64-dot
    int el  = grp >> 1;               // edge-in-batch 0..1
    int top = grp & 1;                // 0: (i,j), 1: (j,i)

    const int* w32 = (const int*)ei_raw;

    // Speculative index fetch, both dtype interpretations, + sniff words.
    int q  = lane & 7;
    int eq = min(base + (q & 3), E - 1);
    int v = 0;
    if (lane < 8)        v = (q < 4) ? w32[eq] : w32[E + eq];
    else if (lane < 16)  v = (q < 4) ? w32[2 * eq] : w32[2 * E + 2 * eq];
    else if (lane < 20)  v = w32[2 * eq + 1];

    bool is64 = ((__ballot_sync(0xffffffffu, v != 0) & 0x000F0000u) == 0u);
    int sb = is64 ? 8 : 0;

    // batch 0 = edges base+0,base+1 ; batch 1 = edges base+2,base+3
    int i0 = __shfl_sync(0xffffffffu, v, sb + el);
    int j0 = __shfl_sync(0xffffffffu, v, sb + 4 + el);
    int i1 = __shfl_sync(0xffffffffu, v, sb + 2 + el);
    int j1 = __shfl_sync(0xffffffffu, v, sb + 6 + el);
    i0 = min(max(i0, 0), N - 1);  j0 = min(max(j0, 0), N - 1);
    i1 = min(max(i1, 0), N - 1);  j1 = min(max(j1, 0), N - 1);

    // scattered noise loads for both batches (m==0 lanes)
    float nz0 = 0.0f, nz1 = 0.0f;
    if (m == 0) {
        nz0 = __ldg(noise + (top ? (j0 * N + i0) : (i0 * N + j0)));
        nz1 = __ldg(noise + (top ? (j1 * N + i1) : (i1 * N + j1)));
    }

    // h rows for both batches: 4 independent LDG.128, minimal wavefronts
    const uint4* A0 = (const uint4*)(g_h16 + (top ? j0 : i0) * 128) + m;
    const uint4* B0 = (const uint4*)(g_h16 + (top ? i0 : j0) * 128) + 8 + m;
    const uint4* A1 = (const uint4*)(g_h16 + (top ? j1 : i1) * 128) + m;
    const uint4* B1 = (const uint4*)(g_h16 + (top ? i1 : j1) * 128) + 8 + m;
    uint4 a0 = __ldg(A0);
    uint4 c0 = __ldg(B0);
    uint4 a1 = __ldg(A1);
    uint4 c1 = __ldg(B1);

    const float4* W = (const float4*)W2 + 2 * m;
    float4 wa = W[0], wb = W[1];

    float s0 = dot8(a0, c0, wa, wb);
    float s1 = dot8(a1, c1, wa, wb);

    // interleaved reduces (two independent chains)
    s0 += __shfl_xor_sync(0xffffffffu, s0, 1);
    s1 += __shfl_xor_sync(0xffffffffu, s1, 1);
    s0 += __shfl_xor_sync(0xffffffffu, s0, 2);
    s1 += __shfl_xor_sync(0xffffffffu, s1, 2);
    s0 += __shfl_xor_sync(0xffffffffu, s0, 4);
    s1 += __shfl_xor_sync(0xffffffffu, s1, 4);

    float g0 = 0.0f, g1 = 0.0f;
    if (m == 0) {
        float inv_beta = 1.0f / tmpp[0];
        float bb = b2[0];
        // logit(n) = log(n/(1-n)) : one MUFU-lg2 instead of two
        float x0 = (__logf(__fdividef(nz0, 1.0f - nz0)) + s0 + bb) * inv_beta;
        float x1 = (__logf(__fdividef(nz1, 1.0f - nz1)) + s1 + bb) * inv_beta;
        g0 = 1.0f / (1.0f + __expf(-x0));
        g1 = 1.0f / (1.0f + __expf(-x1));
    }
    // combine the two directions of each edge: grp0<->grp1 (xor 8)
    float go0 = __shfl_xor_sync(0xffffffffu, g0, 8);
    float go1 = __shfl_xor_sync(0xffffffffu, g1, 8);
    if ((lane & 15) == 0) {       // lane 0 (el=0), lane 16 (el=1)
        int e0 = base + el;
        int e1 = base + 2 + el;
        if (e0 < E) out[e0] = 0.5f * (g0 + go0);
        if (e1 < E) out[e1] = 0.5f * (g1 + go1);
    }
}

// ---------------------------------------------------------------------------
extern "C" void kernel_launch(void* const* d_in, const int* in_sizes, int n_in,
                              void* d_out, int out_size)
{
    const float* embed = (const float*)d_in[0];
    const void*  ei    = d_in[1];
    const float* noise = (const float*)d_in[2];
    const float* tmp   = (const float*)d_in[3];
    const float* W1    = (const float*)d_in[4];
    const float* b1    = (const float*)d_in[5];
    const float* W2    = (const float*)d_in[6];
    const float* b2    = (const float*)d_in[7];
    float*       out   = (float*)d_out;

    int N = in_sizes[0] / 64;      // 1500
    int E = in_sizes[1] / 2;       // 65536

    precompute_h<<<(N + 7) / 8, 256>>>(embed, W1, b1, N);

    // 4 edges per warp, 8 warps per block -> 32 edges per block
    int blocks = (E + 31) / 32;
    edge_gate<<<blocks, 256>>>(ei, noise, tmp, W2, b2, out, N, E);
}

// round 14
// speedup vs baseline: 1.0481x; 1.0481x over previous
#include <cuda_runtime.h>
#include <cuda_fp16.h>

// Inputs (metadata order):
//  0 embed  [N,64] f32          (N=1500)
//  1 edge_index [2,E]           (E=65536; int32 OR int64, per-warp sniffed)
//  2 noise  [N*N] f32
//  3 tmp    [1] f32
//  4 W1     [128,64] f32
//  5 b1     [64] f32
//  6 W2     [64,1] f32
//  7 b2     [1] f32
// Output: edge_mask [E] f32

#define MAXN 1500
#define LOG2E 1.4426950408889634f

// Per node n, row of 128 halfs: [0:64) = h1[n]+b1, [64:128) = h2[n]  (384 KB)
__device__ __align__(256) __half g_h16[MAXN * 128];

// ---------------------------------------------------------------------------
// Kernel 1: h table (fp16). 8 nodes per 256-thread block -> 188 blocks.
// ---------------------------------------------------------------------------
__global__ void __launch_bounds__(256) precompute_h(
    const float* __restrict__ embed,
    const float* __restrict__ W1,
    const float* __restrict__ b1,
    int N)
{
    __shared__ float se[8 * 64];
    int t  = threadIdx.x;
    int n0 = blockIdx.x * 8;

#pragma unroll
    for (int idx = t; idx < 512; idx += 256) {
        int nl = idx >> 6, f = idx & 63;
        se[idx] = (n0 + nl < N) ? embed[(n0 + nl) * 64 + f] : 0.0f;
    }
    __syncthreads();

    int nl   = t >> 5;            // node-local 0..7
    int half = (t >> 4) & 1;      // 0 -> h1, 1 -> h2
    int k0   = (t & 15) * 4;      // 4 adjacent k
    int node = n0 + nl;

    const float* es = se + nl * 64;
    float4 s = make_float4(0.f, 0.f, 0.f, 0.f);
#pragma unroll
    for (int f = 0; f < 64; f++) {
        float e = es[f];
        float4 w = *(const float4*)&W1[(half * 64 + f) * 64 + k0];
        s.x = fmaf(e, w.x, s.x);
        s.y = fmaf(e, w.y, s.y);
        s.z = fmaf(e, w.z, s.z);
        s.w = fmaf(e, w.w, s.w);
    }
    if (half == 0) {
        float4 bb = *(const float4*)&b1[k0];
        s.x += bb.x; s.y += bb.y; s.z += bb.z; s.w += bb.w;
    }
    if (node < N) {
        __half2 lo = __floats2half2_rn(s.x, s.y);
        __half2 hi = __floats2half2_rn(s.z, s.w);
        uint2 p; p.x = *(unsigned*)&lo; p.y = *(unsigned*)&hi;
        *(uint2*)&g_h16[node * 128 + half * 64 + k0] = p;
    }
}

// 8 halfs (one uint4 of fp16 h) -> relu(a+c) dot W2[8]
__device__ __forceinline__ float dot8(uint4 a, uint4 c, float4 wa, float4 wb)
{
    const __half2* ah = (const __half2*)&a;
    const __half2* ch = (const __half2*)&c;
    const __half2  z  = __float2half2_rn(0.0f);
    float2 f0 = __half22float2(__hmax2(__hadd2(ah[0], ch[0]), z));
    float2 f1 = __half22float2(__hmax2(__hadd2(ah[1], ch[1]), z));
    float2 f2 = __half22float2(__hmax2(__hadd2(ah[2], ch[2]), z));
    float2 f3 = __half22float2(__hmax2(__hadd2(ah[3], ch[3]), z));
    float s = f0.x * wa.x;
    s = fmaf(f0.y, wa.y, s);
    s = fmaf(f1.x, wa.z, s);
    s = fmaf(f1.y, wa.w, s);
    s = fmaf(f2.x, wb.x, s);
    s = fmaf(f2.y, wb.y, s);
    s = fmaf(f3.x, wb.z, s);
    s = fmaf(f3.y, wb.w, s);
    return s;
}

// ---------------------------------------------------------------------------
// Kernel 2: 4 edges per warp = 2 software-pipelined batches, 8 lanes per
// h-row. EXACT=true when E % 32 == 0 (no bounds checks, no index clamps).
// ---------------------------------------------------------------------------
template <bool EXACT>
__global__ void __launch_bounds__(256) edge_gate(
    const void* __restrict__ ei_raw,
    const float* __restrict__ noise,
    const float* __restrict__ tmpp,
    const float* __restrict__ W2,
    const float* __restrict__ b2,
    float* __restrict__ out,
    int N, int E)
{
    int tid   = threadIdx.x;
    int lane  = tid & 31;
    int gwarp = (blockIdx.x * blockDim.x + tid) >> 5;
    int base  = gwarp * 4;            // 4 edges per warp

    int grp = lane >> 3;              // direction 0..3 (within a batch)
    int m   = lane & 7;               // eighth of the 64-dot
    int el  = grp >> 1;               // edge-in-batch 0..1
    int top = grp & 1;                // 0: (i,j), 1: (j,i)

    const int* w32 = (const int*)ei_raw;

    // scalar params hoisted: ready long before the tail needs them
    float invb = 1.0f / tmpp[0];
    float bb   = b2[0];

    // Speculative index fetch, both dtype interpretations, + sniff words.
    int q  = lane & 7;
    int eq = base + (q & 3);
    if (!EXACT) eq = min(eq, E - 1);
    int v = 0;
    if (lane < 8)        v = (q < 4) ? w32[eq] : w32[E + eq];
    else if (lane < 16)  v = (q < 4) ? w32[2 * eq] : w32[2 * E + 2 * eq];
    else if (lane < 20)  v = w32[2 * eq + 1];

    bool is64 = ((__ballot_sync(0xffffffffu, v != 0) & 0x000F0000u) == 0u);
    int sb = is64 ? 8 : 0;

    // batch 0 = edges base+0,base+1 ; batch 1 = edges base+2,base+3
    int i0 = __shfl_sync(0xffffffffu, v, sb + el);
    int j0 = __shfl_sync(0xffffffffu, v, sb + 4 + el);
    int i1 = __shfl_sync(0xffffffffu, v, sb + 2 + el);
    int j1 = __shfl_sync(0xffffffffu, v, sb + 6 + el);
    if (!EXACT) {                    // defensive clamps only in generic path
        i0 = min(max(i0, 0), N - 1);  j0 = min(max(j0, 0), N - 1);
        i1 = min(max(i1, 0), N - 1);  j1 = min(max(j1, 0), N - 1);
    }

    // scattered noise loads for both batches (m==0 lanes)
    float nz0 = 0.0f, nz1 = 0.0f;
    if (m == 0) {
        nz0 = __ldg(noise + (top ? (j0 * N + i0) : (i0 * N + j0)));
        nz1 = __ldg(noise + (top ? (j1 * N + i1) : (i1 * N + j1)));
    }

    // h rows for both batches: 4 independent LDG.128, minimal wavefronts
    uint4 a0 = __ldg((const uint4*)(g_h16 + (top ? j0 : i0) * 128) + m);
    uint4 c0 = __ldg((const uint4*)(g_h16 + (top ? i0 : j0) * 128) + 8 + m);
    uint4 a1 = __ldg((const uint4*)(g_h16 + (top ? j1 : i1) * 128) + m);
    uint4 c1 = __ldg((const uint4*)(g_h16 + (top ? i1 : j1) * 128) + 8 + m);

    const float4* W = (const float4*)W2 + 2 * m;
    float4 wa = W[0], wb = W[1];

    float s0 = dot8(a0, c0, wa, wb);
    float s1 = dot8(a1, c1, wa, wb);

    // interleaved reduces (two independent chains)
    s0 += __shfl_xor_sync(0xffffffffu, s0, 1);
    s1 += __shfl_xor_sync(0xffffffffu, s1, 1);
    s0 += __shfl_xor_sync(0xffffffffu, s0, 2);
    s1 += __shfl_xor_sync(0xffffffffu, s1, 2);
    s0 += __shfl_xor_sync(0xffffffffu, s0, 4);
    s1 += __shfl_xor_sync(0xffffffffu, s1, 4);

    float g0 = 0.0f, g1 = 0.0f;
    if (m == 0) {
        // base-2 gate: t = (log2(n/(1-n)) + (s+bb)*log2e)/beta
        //              g = 1 / (1 + 2^-t)
        float t0 = fmaf(s0 + bb, LOG2E,
                        __log2f(__fdividef(nz0, 1.0f - nz0))) * invb;
        float t1 = fmaf(s1 + bb, LOG2E,
                        __log2f(__fdividef(nz1, 1.0f - nz1))) * invb;
        g0 = __fdividef(1.0f, 1.0f + exp2f(-t0));
        g1 = __fdividef(1.0f, 1.0f + exp2f(-t1));
    }
    // combine the two directions of each edge: grp0<->grp1 (xor 8)
    float go0 = __shfl_xor_sync(0xffffffffu, g0, 8);
    float go1 = __shfl_xor_sync(0xffffffffu, g1, 8);
    if ((lane & 15) == 0) {       // lane 0 (el=0), lane 16 (el=1)
        int e0 = base + el;
        int e1 = base + 2 + el;
        if (EXACT || e0 < E) out[e0] = 0.5f * (g0 + go0);
        if (EXACT || e1 < E) out[e1] = 0.5f * (g1 + go1);
    }
}

// ---------------------------------------------------------------------------
extern "C" void kernel_launch(void* const* d_in, const int* in_sizes, int n_in,
                              void* d_out, int out_size)
{
    const float* embed = (const float*)d_in[0];
    const void*  ei    = d_in[1];
    const float* noise = (const float*)d_in[2];
    const float* tmp   = (const float*)d_in[3];
    const float* W1    = (const float*)d_in[4];
    const float* b1    = (const float*)d_in[5];
    const float* W2    = (const float*)d_in[6];
    const float* b2    = (const float*)d_in[7];
    float*       out   = (float*)d_out;

    int N = in_sizes[0] / 64;      // 1500
    int E = in_sizes[1] / 2;       // 65536

    precompute_h<<<(N + 7) / 8, 256>>>(embed, W1, b1, N);

    if ((E & 31) == 0) {
        edge_gate<true><<<E / 32, 256>>>(ei, noise, tmp, W2, b2, out, N, E);
    } else {
        edge_gate<false><<<(E + 31) / 32, 256>>>(ei, noise, tmp, W2, b2,
                                                 out, N, E);
    }
}

// round 15
// speedup vs baseline: 1.0692x; 1.0201x over previous
#include <cuda_runtime.h>
#include <cuda_fp16.h>

// Inputs (metadata order):
//  0 embed  [N,64] f32          (N=1500)
//  1 edge_index [2,E]           (E=65536; int32 OR int64, per-warp sniffed)
//  2 noise  [N*N] f32
//  3 tmp    [1] f32
//  4 W1     [128,64] f32
//  5 b1     [64] f32
//  6 W2     [64,1] f32
//  7 b2     [1] f32
// Output: edge_mask [E] f32
//
// Two launches:
//  prep:      blocks [0,P)  -> h table (fp16, per-node rows)
//             blocks [P,..) -> decode indices + gather noise + log2-logit
//             (independent halves -> run concurrently, no barrier needed)
//  edge_gate: lean gather over L2-resident staging + h table.

#define MAXN 1500
#define MAXE (1 << 17)
#define LOG2E 1.4426950408889634f

// Per node n, row of 128 halfs: [0:64) = h1[n]+b1, [64:128) = h2[n]  (384 KB)
__device__ __align__(256) __half g_h16[MAXN * 128];
// Staging: packed (i<<16)|j per edge; log2-logit of noise per direction.
__device__ unsigned g_pair[MAXE];
__device__ float    g_logit[2 * MAXE];

// ---------------------------------------------------------------------------
// Kernel 1: prep. Producer blocks + gather blocks in one launch.
// ---------------------------------------------------------------------------
__global__ void __launch_bounds__(256) prep(
    const float* __restrict__ embed,
    const float* __restrict__ W1,
    const float* __restrict__ b1,
    const void* __restrict__ ei_raw,
    const float* __restrict__ noise,
    int N, int E, int P)
{
    int t = threadIdx.x;

    if ((int)blockIdx.x >= P) {
        // ---------- gather: one thread per direction ----------
        int d = ((int)blockIdx.x - P) * 256 + t;
        if (d >= 2 * E) return;
        int e   = d >> 1;
        int top = d & 1;

        const int* w32 = (const int*)ei_raw;
        // dtype sniff: odd word of the int64-src reading; warp covers 16
        // edges -> P(false int64) ~ 1500^-16.
        int hi = w32[2 * e + 1];
        bool is64 = (__ballot_sync(0xffffffffu, hi != 0) == 0u);

        int i, j;
        if (is64) { i = w32[2 * e];  j = w32[2 * E + 2 * e]; }
        else      { i = w32[e];      j = w32[E + e]; }
        i = min(max(i, 0), N - 1);
        j = min(max(j, 0), N - 1);

        if (!top) g_pair[e] = ((unsigned)i << 16) | (unsigned)j;

        float nz = __ldg(noise + (top ? (j * N + i) : (i * N + j)));
        g_logit[d] = __log2f(__fdividef(nz, 1.0f - nz));
        return;
    }

    // ---------- producer: 8 nodes per block ----------
    __shared__ float se[8 * 64];
    int n0 = blockIdx.x * 8;

#pragma unroll
    for (int idx = t; idx < 512; idx += 256) {
        int nl = idx >> 6, f = idx & 63;
        se[idx] = (n0 + nl < N) ? embed[(n0 + nl) * 64 + f] : 0.0f;
    }
    __syncthreads();

    int nl   = t >> 5;            // node-local 0..7
    int half = (t >> 4) & 1;      // 0 -> h1, 1 -> h2
    int k0   = (t & 15) * 4;      // 4 adjacent k
    int node = n0 + nl;

    const float* es = se + nl * 64;
    float4 s = make_float4(0.f, 0.f, 0.f, 0.f);
#pragma unroll
    for (int f = 0; f < 64; f++) {
        float e = es[f];
        float4 w = *(const float4*)&W1[(half * 64 + f) * 64 + k0];
        s.x = fmaf(e, w.x, s.x);
        s.y = fmaf(e, w.y, s.y);
        s.z = fmaf(e, w.z, s.z);
        s.w = fmaf(e, w.w, s.w);
    }
    if (half == 0) {
        float4 bb = *(const float4*)&b1[k0];
        s.x += bb.x; s.y += bb.y; s.z += bb.z; s.w += bb.w;
    }
    if (node < N) {
        __half2 lo = __floats2half2_rn(s.x, s.y);
        __half2 hi = __floats2half2_rn(s.z, s.w);
        uint2 p; p.x = *(unsigned*)&lo; p.y = *(unsigned*)&hi;
        *(uint2*)&g_h16[node * 128 + half * 64 + k0] = p;
    }
}

// 8 halfs (one uint4 of fp16 h) -> relu(a+c) dot W2[8]
__device__ __forceinline__ float dot8(uint4 a, uint4 c, float4 wa, float4 wb)
{
    const __half2* ah = (const __half2*)&a;
    const __half2* ch = (const __half2*)&c;
    const __half2  z  = __float2half2_rn(0.0f);
    float2 f0 = __half22float2(__hmax2(__hadd2(ah[0], ch[0]), z));
    float2 f1 = __half22float2(__hmax2(__hadd2(ah[1], ch[1]), z));
    float2 f2 = __half22float2(__hmax2(__hadd2(ah[2], ch[2]), z));
    float2 f3 = __half22float2(__hmax2(__hadd2(ah[3], ch[3]), z));
    float s = f0.x * wa.x;
    s = fmaf(f0.y, wa.y, s);
    s = fmaf(f1.x, wa.z, s);
    s = fmaf(f1.y, wa.w, s);
    s = fmaf(f2.x, wb.x, s);
    s = fmaf(f2.y, wb.y, s);
    s = fmaf(f3.x, wb.z, s);
    s = fmaf(f3.y, wb.w, s);
    return s;
}

// ---------------------------------------------------------------------------
// Kernel 2: lean edge gate. 4 edges per warp = 2 batches, 8 lanes per h-row.
// All irregular decode/gather work was staged by prep; loads here are
// L2-resident (g_pair, g_logit, g_h16).
// ---------------------------------------------------------------------------
template <bool EXACT>
__global__ void __launch_bounds__(256) edge_gate(
    const float* __restrict__ tmpp,
    const float* __restrict__ W2,
    const float* __restrict__ b2,
    float* __restrict__ out,
    int N, int E)
{
    int tid   = threadIdx.x;
    int lane  = tid & 31;
    int gwarp = (blockIdx.x * blockDim.x + tid) >> 5;
    int base  = gwarp * 4;            // 4 edges per warp

    int grp = lane >> 3;              // direction 0..3 (within a batch)
    int m   = lane & 7;               // eighth of the 64-dot
    int el  = grp >> 1;               // edge-in-batch 0..1
    int top = grp & 1;                // 0: (i,j), 1: (j,i)

    float invb = 1.0f / tmpp[0];
    float bb   = b2[0];

    int e0 = base + el;
    int e1 = base + 2 + el;
    if (!EXACT) { e0 = min(e0, E - 1); e1 = min(e1, E - 1); }

    // packed node pairs (8 lanes same address -> broadcast)
    unsigned p0 = __ldg(g_pair + e0);
    unsigned p1 = __ldg(g_pair + e1);

    // staged log2-logits (m==0 lanes)
    float L0 = 0.0f, L1 = 0.0f;
    if (m == 0) {
        L0 = __ldg(g_logit + 2 * e0 + top);
        L1 = __ldg(g_logit + 2 * e1 + top);
    }

    int i0 = p0 >> 16, j0 = p0 & 0xFFFF;
    int i1 = p1 >> 16, j1 = p1 & 0xFFFF;

    // h rows: 4 independent LDG.128 (8 lanes cover one 256B row half)
    uint4 a0 = __ldg((const uint4*)(g_h16 + (top ? j0 : i0) * 128) + m);
    uint4 c0 = __ldg((const uint4*)(g_h16 + (top ? i0 : j0) * 128) + 8 + m);
    uint4 a1 = __ldg((const uint4*)(g_h16 + (top ? j1 : i1) * 128) + m);
    uint4 c1 = __ldg((const uint4*)(g_h16 + (top ? i1 : j1) * 128) + 8 + m);

    const float4* W = (const float4*)W2 + 2 * m;
    float4 wa = W[0], wb = W[1];

    float s0 = dot8(a0, c0, wa, wb);
    float s1 = dot8(a1, c1, wa, wb);

    // interleaved reduces (two independent chains)
    s0 += __shfl_xor_sync(0xffffffffu, s0, 1);
    s1 += __shfl_xor_sync(0xffffffffu, s1, 1);
    s0 += __shfl_xor_sync(0xffffffffu, s0, 2);
    s1 += __shfl_xor_sync(0xffffffffu, s1, 2);
    s0 += __shfl_xor_sync(0xffffffffu, s0, 4);
    s1 += __shfl_xor_sync(0xffffffffu, s1, 4);

    float g0 = 0.0f, g1 = 0.0f;
    if (m == 0) {
        // x2 = (L + (s+bb)*log2e)/beta ; g = 1/(1+2^-x2)
        float t0 = fmaf(s0 + bb, LOG2E, L0) * invb;
        float t1 = fmaf(s1 + bb, LOG2E, L1) * invb;
        g0 = __fdividef(1.0f, 1.0f + exp2f(-t0));
        g1 = __fdividef(1.0f, 1.0f + exp2f(-t1));
    }
    // combine the two directions of each edge: grp0<->grp1 (xor 8)
    float go0 = __shfl_xor_sync(0xffffffffu, g0, 8);
    float go1 = __shfl_xor_sync(0xffffffffu, g1, 8);
    if ((lane & 15) == 0) {       // lane 0 (el=0), lane 16 (el=1)
        int ew0 = base + el;
        int ew1 = base + 2 + el;
        if (EXACT || ew0 < E) out[ew0] = 0.5f * (g0 + go0);
        if (EXACT || ew1 < E) out[ew1] = 0.5f * (g1 + go1);
    }
}

// ---------------------------------------------------------------------------
extern "C" void kernel_launch(void* const* d_in, const int* in_sizes, int n_in,
                              void* d_out, int out_size)
{
    const float* embed = (const float*)d_in[0];
    const void*  ei    = d_in[1];
    const float* noise = (const float*)d_in[2];
    const float* tmp   = (const float*)d_in[3];
    const float* W1    = (const float*)d_in[4];
    const float* b1    = (const float*)d_in[5];
    const float* W2    = (const float*)d_in[6];
    const float* b2    = (const float*)d_in[7];
    float*       out   = (float*)d_out;

    int N = in_sizes[0] / 64;      // 1500
    int E = in_sizes[1] / 2;       // 65536 (<= MAXE)

    int P  = (N + 7) / 8;                  // producer blocks
    int Gd = (2 * E + 255) / 256;          // gather blocks
    prep<<<P + Gd, 256>>>(embed, W1, b1, ei, noise, N, E, P);

    if ((E & 31) == 0) {
        edge_gate<true><<<E / 32, 256>>>(tmp, W2, b2, out, N, E);
    } else {
        edge_gate<false><<<(E + 31) / 32, 256>>>(tmp, W2, b2, out, N, E);
    }
}